// round 2
// baseline (speedup 1.0000x reference)
#include <cuda_runtime.h>

// ---------------------------------------------------------------------------
// QuantizedLMHead:
//   s      = x @ U                  [N=4096, D=2048]
//   z      = quantize(s / lambda_x) to nearest of 16 sorted codebook values
//   A      = z * (lambda_x * lambda_w)
//   logits = A @ Z_w                [N=4096, V=32000]
//
// Round 1: fp32 SGEMM (128x128x16 tile, 8x8 microtile, 256 threads), with the
// quantization fused into GEMM1's epilogue. Scratch A lives in a __device__
// global (no allocation).
// ---------------------------------------------------------------------------

#define BM 128
#define BN 128
#define BK 16
#define TM 8
#define TN 8
// (BM/TM)*(BN/TN) = 256 threads

__device__ float g_A[4096 * 2048];   // 33.5 MB scratch for quantized activations

template <bool QUANT>
__global__ __launch_bounds__(256)
void sgemm_kernel(const float* __restrict__ A_in, const float* __restrict__ B,
                  float* __restrict__ C_out, int M, int N, int K,
                  const float* __restrict__ lx, const float* __restrict__ lw,
                  const float* __restrict__ cb)
{
    // GEMM1 (QUANT): reads A_in (=x), writes g_A.
    // GEMM2        : reads g_A,      writes C_out (=logits).
    const float* A = QUANT ? A_in : (const float*)g_A;
    float*       C = QUANT ? (float*)g_A : C_out;

    __shared__ float As[BK][BM];
    __shared__ float Bs[BK][BN];

    const int tid  = threadIdx.x;
    const int bm   = blockIdx.y;
    const int bn   = blockIdx.x;
    const int row0 = (tid / 16) * TM;   // 0..120
    const int col0 = (tid % 16) * TN;   // 0..120

    const float* Ag = A + (size_t)bm * BM * K;
    const float* Bg = B + (size_t)bn * BN;

    float acc[TM][TN];
    #pragma unroll
    for (int i = 0; i < TM; ++i)
        #pragma unroll
        for (int j = 0; j < TN; ++j)
            acc[i][j] = 0.0f;

    float a_frag[TM], b_frag[TN];

    for (int k0 = 0; k0 < K; k0 += BK) {
        // --- load A tile (BM x BK), store transposed As[k][m] ---
        // 512 float4 per tile; 2 per thread.
        #pragma unroll
        for (int l = 0; l < 2; ++l) {
            int idx = tid + l * 256;
            int r   = idx >> 2;          // 0..127
            int c   = (idx & 3) * 4;     // 0,4,8,12
            float4 v = *reinterpret_cast<const float4*>(Ag + (size_t)r * K + k0 + c);
            As[c + 0][r] = v.x;
            As[c + 1][r] = v.y;
            As[c + 2][r] = v.z;
            As[c + 3][r] = v.w;
        }
        // --- load B tile (BK x BN) ---
        #pragma unroll
        for (int l = 0; l < 2; ++l) {
            int idx = tid + l * 256;
            int r   = idx >> 5;          // 0..15
            int c   = (idx & 31) * 4;    // 0..124
            *reinterpret_cast<float4*>(&Bs[r][c]) =
                *reinterpret_cast<const float4*>(Bg + (size_t)(k0 + r) * N + c);
        }
        __syncthreads();

        #pragma unroll
        for (int kk = 0; kk < BK; ++kk) {
            #pragma unroll
            for (int i = 0; i < TM; i += 4)
                *reinterpret_cast<float4*>(&a_frag[i]) =
                    *reinterpret_cast<const float4*>(&As[kk][row0 + i]);
            #pragma unroll
            for (int j = 0; j < TN; j += 4)
                *reinterpret_cast<float4*>(&b_frag[j]) =
                    *reinterpret_cast<const float4*>(&Bs[kk][col0 + j]);
            #pragma unroll
            for (int i = 0; i < TM; ++i)
                #pragma unroll
                for (int j = 0; j < TN; ++j)
                    acc[i][j] = fmaf(a_frag[i], b_frag[j], acc[i][j]);
        }
        __syncthreads();
    }

    if (QUANT) {
        // 16-entry sorted codebook: nearest-neighbor via 15 midpoint selects.
        // Advance only on z > mid  ->  exact-tie picks lower index, matching
        // jnp.argmin first-min semantics.
        float c[16];
        #pragma unroll
        for (int t = 0; t < 16; ++t) c[t] = cb[t];

        #pragma unroll
        for (int j = 0; j < TN; ++j) {
            int   col   = bn * BN + col0 + j;
            float l     = lx[col];
            float safe  = (fabsf(l) < 1e-8f) ? 1e-8f : l;
            float coeff = l * lw[col];
            #pragma unroll
            for (int i = 0; i < TM; ++i) {
                float z = acc[i][j] / safe;
                float q = c[0];
                #pragma unroll
                for (int t = 0; t < 15; ++t) {
                    float mid = 0.5f * (c[t] + c[t + 1]);
                    q = (z > mid) ? c[t + 1] : q;
                }
                acc[i][j] = q * coeff;
            }
        }
    }

    // --- store C tile ---
    #pragma unroll
    for (int i = 0; i < TM; ++i) {
        float* Cp = C + (size_t)(bm * BM + row0 + i) * N + bn * BN + col0;
        *reinterpret_cast<float4*>(Cp)     = *reinterpret_cast<float4*>(&acc[i][0]);
        *reinterpret_cast<float4*>(Cp + 4) = *reinterpret_cast<float4*>(&acc[i][4]);
    }
}

extern "C" void kernel_launch(void* const* d_in, const int* in_sizes, int n_in,
                              void* d_out, int out_size)
{
    const float* x  = (const float*)d_in[0];   // [B,S,D] fp32
    const float* U  = (const float*)d_in[1];   // [D,D]
    const float* lx = (const float*)d_in[2];   // [D]
    const float* lw = (const float*)d_in[3];   // [D]
    const float* Zw = (const float*)d_in[4];   // [D,V]
    const float* cb = (const float*)d_in[5];   // [16] sorted

    float* out = (float*)d_out;                // [B*S, V]

    const int D  = in_sizes[2];                // 2048
    const int Nt = in_sizes[0] / D;            // 4096
    const int V  = in_sizes[4] / D;            // 32000

    dim3 block(256);

    // GEMM1 + quantize epilogue: x[Nt,D] @ U[D,D] -> g_A[Nt,D]
    sgemm_kernel<true><<<dim3(D / BN, Nt / BM), block>>>(
        x, U, nullptr, Nt, D, D, lx, lw, cb);

    // GEMM2: g_A[Nt,D] @ Zw[D,V] -> out[Nt,V]
    sgemm_kernel<false><<<dim3(V / BN, Nt / BM), block>>>(
        nullptr, Zw, out, Nt, V, D, nullptr, nullptr, nullptr);
}

// round 5
// speedup vs baseline: 3.0903x; 3.0903x over previous
#include <cuda_runtime.h>
#include <cuda_fp16.h>
#include <cstdint>

// ---------------------------------------------------------------------------
// QuantizedLMHead (sm_103, no 'a' features available at harness ptxas target):
//   Wprep: W' = (lx*lw)*Z_w, split fp16 hi/lo -> g_Wx scratch [4096, 32000]
//   GEMM1: s = x @ U (fp32 SGEMM) + nearest-codebook quantize -> fp16 g_Aq
//          (NOTE: coeff folded into W ONLY — R3 applied it twice)
//   GEMM2: logits = A @ Wh + A @ Wl via mma.sync m16n8k16 fp16 / fp32 acc,
//          K_ext=4096 with A k-index wrapped (k & 2047).
// ---------------------------------------------------------------------------

#define D_DIM 2048
#define V_DIM 32000
#define N_TOK 4096
#define K_EXT 4096

__device__ __align__(256) __half g_Aq[(size_t)N_TOK * D_DIM];   // 16.8 MB
__device__ __align__(256) __half g_Wx[(size_t)K_EXT * V_DIM];   // 262 MB

// ---------------- PTX helpers (baseline sm_80-level) -----------------------
__device__ __forceinline__ uint32_t smem_u32(const void* p) {
    uint32_t a;
    asm("{ .reg .u64 t; cvta.to.shared.u64 t, %1; cvt.u32.u64 %0, t; }" : "=r"(a) : "l"(p));
    return a;
}
__device__ __forceinline__ void cp16(uint32_t dst, const void* src) {
    asm volatile("cp.async.cg.shared.global [%0], [%1], 16;" :: "r"(dst), "l"(src));
}
#define CP_COMMIT() asm volatile("cp.async.commit_group;" ::: "memory")
#define CP_WAIT2()  asm volatile("cp.async.wait_group 2;" ::: "memory")

__device__ __forceinline__ void ldsm4(uint32_t* r, uint32_t addr) {
    asm volatile("ldmatrix.sync.aligned.m8n8.x4.shared.b16 {%0,%1,%2,%3}, [%4];"
                 : "=r"(r[0]), "=r"(r[1]), "=r"(r[2]), "=r"(r[3]) : "r"(addr));
}
__device__ __forceinline__ void ldsm4t(uint32_t* r, uint32_t addr) {
    asm volatile("ldmatrix.sync.aligned.m8n8.x4.trans.shared.b16 {%0,%1,%2,%3}, [%4];"
                 : "=r"(r[0]), "=r"(r[1]), "=r"(r[2]), "=r"(r[3]) : "r"(addr));
}
__device__ __forceinline__ void mma16816(float* c, const uint32_t* a, uint32_t b0, uint32_t b1) {
    asm volatile("mma.sync.aligned.m16n8k16.row.col.f32.f16.f16.f32 "
                 "{%0,%1,%2,%3}, {%4,%5,%6,%7}, {%8,%9}, {%0,%1,%2,%3};"
                 : "+f"(c[0]), "+f"(c[1]), "+f"(c[2]), "+f"(c[3])
                 : "r"(a[0]), "r"(a[1]), "r"(a[2]), "r"(a[3]), "r"(b0), "r"(b1));
}

// ---------------------------------------------------------------------------
// W prep: fold coeff, split fp16 hi/lo.  grid (V/256, D), block 256.
// ---------------------------------------------------------------------------
__global__ __launch_bounds__(256)
void wprep_kernel(const float* __restrict__ Zw, const float* __restrict__ lx,
                  const float* __restrict__ lw)
{
    const int v = blockIdx.x * 256 + threadIdx.x;
    const int k = blockIdx.y;
    const float coeff = lx[k] * lw[k];
    float w = coeff * Zw[(size_t)k * V_DIM + v];
    __half wh = __float2half(w);
    __half wl = __float2half(w - __half2float(wh));
    g_Wx[(size_t)k * V_DIM + v] = wh;
    g_Wx[(size_t)(k + D_DIM) * V_DIM + v] = wl;
}

// ---------------------------------------------------------------------------
// GEMM1 (x @ U) fp32 + quantize -> fp16 A scratch (codebook value ONLY).
// 128x128x16 tile, 8x8 microtile, 256 threads. grid (D/128, N_TOK/128).
// ---------------------------------------------------------------------------
__global__ __launch_bounds__(256)
void gemm1_quant_kernel(const float* __restrict__ A, const float* __restrict__ B,
                        const float* __restrict__ lx, const float* __restrict__ cb)
{
    __shared__ float As[16][128];
    __shared__ float Bs[16][128];

    const int tid  = threadIdx.x;
    const int bm   = blockIdx.y;
    const int bn   = blockIdx.x;
    const int row0 = (tid / 16) * 8;
    const int col0 = (tid % 16) * 8;
    const int K = D_DIM, N = D_DIM;

    const float* Ag = A + (size_t)bm * 128 * K;
    const float* Bg = B + (size_t)bn * 128;

    float acc[8][8];
    #pragma unroll
    for (int i = 0; i < 8; ++i)
        #pragma unroll
        for (int j = 0; j < 8; ++j) acc[i][j] = 0.0f;

    float a_frag[8], b_frag[8];

    for (int k0 = 0; k0 < K; k0 += 16) {
        #pragma unroll
        for (int ld = 0; ld < 2; ++ld) {
            int idx = tid + ld * 256;
            int r = idx >> 2, c = (idx & 3) * 4;
            float4 v = *reinterpret_cast<const float4*>(Ag + (size_t)r * K + k0 + c);
            As[c + 0][r] = v.x; As[c + 1][r] = v.y; As[c + 2][r] = v.z; As[c + 3][r] = v.w;
        }
        #pragma unroll
        for (int ld = 0; ld < 2; ++ld) {
            int idx = tid + ld * 256;
            int r = idx >> 5, c = (idx & 31) * 4;
            *reinterpret_cast<float4*>(&Bs[r][c]) =
                *reinterpret_cast<const float4*>(Bg + (size_t)(k0 + r) * N + c);
        }
        __syncthreads();
        #pragma unroll
        for (int kk = 0; kk < 16; ++kk) {
            #pragma unroll
            for (int i = 0; i < 8; i += 4)
                *reinterpret_cast<float4*>(&a_frag[i]) = *reinterpret_cast<const float4*>(&As[kk][row0 + i]);
            #pragma unroll
            for (int j = 0; j < 8; j += 4)
                *reinterpret_cast<float4*>(&b_frag[j]) = *reinterpret_cast<const float4*>(&Bs[kk][col0 + j]);
            #pragma unroll
            for (int i = 0; i < 8; ++i)
                #pragma unroll
                for (int j = 0; j < 8; ++j)
                    acc[i][j] = fmaf(a_frag[i], b_frag[j], acc[i][j]);
        }
        __syncthreads();
    }

    // epilogue: nearest sorted codebook entry (tie -> lower index, matching
    // argmin-first semantics). Store bare codebook value in fp16; coeff lives
    // in W only.
    float c[16];
    #pragma unroll
    for (int t = 0; t < 16; ++t) c[t] = cb[t];

    const int dbase = bn * 128 + col0;
    float safe[8];
    #pragma unroll
    for (int j = 0; j < 8; ++j) {
        float lv = lx[dbase + j];
        safe[j] = (fabsf(lv) < 1e-8f) ? 1e-8f : lv;
    }

    #pragma unroll
    for (int i = 0; i < 8; ++i) {
        __half hv[8];
        #pragma unroll
        for (int j = 0; j < 8; ++j) {
            float z = acc[i][j] / safe[j];
            float q = c[0];
            #pragma unroll
            for (int t = 0; t < 15; ++t) {
                float mid = 0.5f * (c[t] + c[t + 1]);
                q = (z > mid) ? c[t + 1] : q;
            }
            hv[j] = __float2half(q);
        }
        *reinterpret_cast<uint4*>(&g_Aq[(size_t)(bm * 128 + row0 + i) * D_DIM + dbase]) =
            *reinterpret_cast<uint4*>(hv);
    }
}

// ---------------------------------------------------------------------------
// GEMM2 — fp16 mma.sync, 128x128 CTA tile, BK=64, 4-stage cp.async.
// 256 threads: 8 warps in 2(m) x 4(n); warp tile 64x32.
// ---------------------------------------------------------------------------
#define BKK 64
#define STAGES 4
#define A_ROW_B 144                     // 64 fp16 + 8 pad = 144B (odd * 16B)
#define B_ROW_B 272                     // 128 fp16 + 8 pad = 272B (odd * 16B)
#define A_STG (128 * A_ROW_B)           // 18432
#define B_STG (64 * B_ROW_B)            // 17408
#define STG_B (A_STG + B_STG)           // 35840
#define SMEM2_TOTAL (STAGES * STG_B)    // 143360

__global__ __launch_bounds__(256, 1)
void gemm2_mma_kernel(float* __restrict__ C)
{
    extern __shared__ __align__(128) unsigned char sm2[];
    const uint32_t sb = smem_u32(sm2);
    const int tid  = threadIdx.x;
    const int lane = tid & 31;
    const int wid  = tid >> 5;
    const int wm   = wid >> 2;          // 0..1
    const int wn   = wid & 3;           // 0..3
    const int m0   = blockIdx.x * 128;  // 32 tiles (fast dim -> A/B L2 reuse)
    const int n0   = blockIdx.y * 128;  // 250 tiles

    float acc[4][4][4];
    #pragma unroll
    for (int mi = 0; mi < 4; ++mi)
        #pragma unroll
        for (int ni = 0; ni < 4; ++ni)
            #pragma unroll
            for (int r = 0; r < 4; ++r) acc[mi][ni][r] = 0.0f;

    auto load_stage = [&](int kt, int slot) {
        const int kb = kt * BKK;
        const int ka = kb & (D_DIM - 1);           // A k wrap (hi/lo passes)
        const uint32_t sa  = sb + slot * STG_B;
        const uint32_t sbB = sa + A_STG;
        #pragma unroll
        for (int i = 0; i < 4; ++i) {
            int cc = tid + i * 256;
            int row = cc >> 3, col = (cc & 7) * 8;
            cp16(sa + row * A_ROW_B + col * 2,
                 g_Aq + (size_t)(m0 + row) * D_DIM + ka + col);
        }
        #pragma unroll
        for (int i = 0; i < 4; ++i) {
            int cc = tid + i * 256;
            int row = cc >> 4, col = (cc & 15) * 8;
            cp16(sbB + row * B_ROW_B + col * 2,
                 g_Wx + (size_t)(kb + row) * V_DIM + n0 + col);
        }
        CP_COMMIT();
    };

    const int KT = K_EXT / BKK;     // 64
    load_stage(0, 0);
    load_stage(1, 1);
    load_stage(2, 2);

    // per-lane ldmatrix address pieces
    const int a_row_l = wm * 64 + (lane & 15);                 // + mi*16
    const int a_k_l   = (lane >> 4) * 8;                       // + ks*16
    const int b_row_l = (lane & 7) + ((lane >> 3) & 1) * 8;    // + ks*16
    const int b_col_l = wn * 32 + ((lane >> 4) & 1) * 8;       // + ni2*16

    for (int kt = 0; kt < KT; ++kt) {
        CP_WAIT2();
        __syncthreads();
        const int slot = kt & (STAGES - 1);
        const uint32_t sa  = sb + slot * STG_B;
        const uint32_t sbb = sa + A_STG;

        #pragma unroll
        for (int ks = 0; ks < 4; ++ks) {
            uint32_t a[4][4], b[2][4];
            #pragma unroll
            for (int mi = 0; mi < 4; ++mi)
                ldsm4(a[mi], sa + (a_row_l + mi * 16) * A_ROW_B + (a_k_l + ks * 16) * 2);
            #pragma unroll
            for (int ni2 = 0; ni2 < 2; ++ni2)
                ldsm4t(b[ni2], sbb + (b_row_l + ks * 16) * B_ROW_B + (b_col_l + ni2 * 16) * 2);
            #pragma unroll
            for (int mi = 0; mi < 4; ++mi)
                #pragma unroll
                for (int ni = 0; ni < 4; ++ni)
                    mma16816(acc[mi][ni], a[mi], b[ni >> 1][2 * (ni & 1)],
                             b[ni >> 1][2 * (ni & 1) + 1]);
        }

        if (kt + STAGES - 1 < KT) load_stage(kt + STAGES - 1, (kt + STAGES - 1) & (STAGES - 1));
        else CP_COMMIT();           // keep group counting uniform
    }

    // epilogue: fp32 accumulators -> C
    #pragma unroll
    for (int mi = 0; mi < 4; ++mi) {
        const int row = m0 + wm * 64 + mi * 16 + (lane >> 2);
        #pragma unroll
        for (int ni = 0; ni < 4; ++ni) {
            const int col = n0 + wn * 32 + ni * 8 + (lane & 3) * 2;
            float2 v0 = make_float2(acc[mi][ni][0], acc[mi][ni][1]);
            float2 v1 = make_float2(acc[mi][ni][2], acc[mi][ni][3]);
            *reinterpret_cast<float2*>(C + (size_t)row * V_DIM + col) = v0;
            *reinterpret_cast<float2*>(C + (size_t)(row + 8) * V_DIM + col) = v1;
        }
    }
}

// ---------------------------------------------------------------------------
extern "C" void kernel_launch(void* const* d_in, const int* in_sizes, int n_in,
                              void* d_out, int out_size)
{
    const float* x  = (const float*)d_in[0];
    const float* U  = (const float*)d_in[1];
    const float* lx = (const float*)d_in[2];
    const float* lw = (const float*)d_in[3];
    const float* Zw = (const float*)d_in[4];
    const float* cb = (const float*)d_in[5];
    float* out = (float*)d_out;

    cudaFuncSetAttribute(gemm2_mma_kernel,
                         cudaFuncAttributeMaxDynamicSharedMemorySize, SMEM2_TOTAL);

    // 1) W' = coeff * Z_w, split hi/lo fp16
    wprep_kernel<<<dim3(V_DIM / 256, D_DIM), 256>>>(Zw, lx, lw);

    // 2) x@U + quantize -> fp16 A (no coeff here!)
    gemm1_quant_kernel<<<dim3(D_DIM / 128, N_TOK / 128), 256>>>(x, U, lx, cb);

    // 3) big GEMM on tensor cores (mma.sync)
    gemm2_mma_kernel<<<dim3(N_TOK / 128, V_DIM / 128), 256, SMEM2_TOTAL>>>(out);
}

// round 6
// speedup vs baseline: 5.3967x; 1.7463x over previous
#include <cuda_runtime.h>
#include <cuda_fp16.h>
#include <cstdint>

// ---------------------------------------------------------------------------
// QuantizedLMHead (sm_103 baseline ISA):
//   Wprep: Wh = fp16((lx*lw)*Z_w)            -> g_Wx [2048, 32000]
//   GEMM1: s = x @ U (fp32 SGEMM) + nearest-codebook quantize -> fp16 g_Aq
//   GEMM2: logits = A @ Wh  (mma.sync m16n8k16, fp32 acc, K=2048)
//   Error budget: quant flips 5.28e-4 (+) A fp16 1.4e-4 (+) W fp16 1.4e-4
//                 ~= 5.7e-4 in quadrature (metric shown to compose in l2).
// ---------------------------------------------------------------------------

#define D_DIM 2048
#define V_DIM 32000
#define N_TOK 4096

__device__ __align__(256) __half g_Aq[(size_t)N_TOK * D_DIM];   // 16.8 MB
__device__ __align__(256) __half g_Wx[(size_t)D_DIM * V_DIM];   // 131 MB

// ---------------- PTX helpers ----------------------------------------------
__device__ __forceinline__ uint32_t smem_u32(const void* p) {
    uint32_t a;
    asm("{ .reg .u64 t; cvta.to.shared.u64 t, %1; cvt.u32.u64 %0, t; }" : "=r"(a) : "l"(p));
    return a;
}
__device__ __forceinline__ void cp16(uint32_t dst, const void* src) {
    asm volatile("cp.async.cg.shared.global [%0], [%1], 16;" :: "r"(dst), "l"(src));
}
#define CP_COMMIT() asm volatile("cp.async.commit_group;" ::: "memory")
#define CP_WAIT1()  asm volatile("cp.async.wait_group 1;" ::: "memory")

__device__ __forceinline__ void ldsm4(uint32_t* r, uint32_t addr) {
    asm volatile("ldmatrix.sync.aligned.m8n8.x4.shared.b16 {%0,%1,%2,%3}, [%4];"
                 : "=r"(r[0]), "=r"(r[1]), "=r"(r[2]), "=r"(r[3]) : "r"(addr));
}
__device__ __forceinline__ void ldsm4t(uint32_t* r, uint32_t addr) {
    asm volatile("ldmatrix.sync.aligned.m8n8.x4.trans.shared.b16 {%0,%1,%2,%3}, [%4];"
                 : "=r"(r[0]), "=r"(r[1]), "=r"(r[2]), "=r"(r[3]) : "r"(addr));
}
__device__ __forceinline__ void mma16816(float* c, const uint32_t* a, uint32_t b0, uint32_t b1) {
    asm volatile("mma.sync.aligned.m16n8k16.row.col.f32.f16.f16.f32 "
                 "{%0,%1,%2,%3}, {%4,%5,%6,%7}, {%8,%9}, {%0,%1,%2,%3};"
                 : "+f"(c[0]), "+f"(c[1]), "+f"(c[2]), "+f"(c[3])
                 : "r"(a[0]), "r"(a[1]), "r"(a[2]), "r"(a[3]), "r"(b0), "r"(b1));
}

// ---------------------------------------------------------------------------
// W prep: Wh = fp16(coeff * Zw). float4-vectorized. 65.536M elems / 4 / 256.
// ---------------------------------------------------------------------------
__global__ __launch_bounds__(256)
void wprep_kernel(const float* __restrict__ Zw, const float* __restrict__ lx,
                  const float* __restrict__ lw)
{
    const int idx = blockIdx.x * 256 + threadIdx.x;      // quad index
    const int k   = idx / (V_DIM / 4);
    const int v4  = idx % (V_DIM / 4);
    const float coeff = __ldg(lx + k) * __ldg(lw + k);
    float4 w = *reinterpret_cast<const float4*>(Zw + (size_t)k * V_DIM + v4 * 4);
    __half h[4];
    h[0] = __float2half(coeff * w.x);
    h[1] = __float2half(coeff * w.y);
    h[2] = __float2half(coeff * w.z);
    h[3] = __float2half(coeff * w.w);
    *reinterpret_cast<uint2*>(g_Wx + (size_t)k * V_DIM + v4 * 4) =
        *reinterpret_cast<uint2*>(h);
}

// ---------------------------------------------------------------------------
// GEMM1 (x @ U) fp32 + quantize -> fp16 codebook values.
// 128x128x16 tile, 8x8 microtile, 256 threads. grid (D/128, N_TOK/128).
// ---------------------------------------------------------------------------
__global__ __launch_bounds__(256)
void gemm1_quant_kernel(const float* __restrict__ A, const float* __restrict__ B,
                        const float* __restrict__ lx, const float* __restrict__ cb)
{
    __shared__ float As[16][128];
    __shared__ float Bs[16][128];

    const int tid  = threadIdx.x;
    const int bm   = blockIdx.y;
    const int bn   = blockIdx.x;
    const int row0 = (tid / 16) * 8;
    const int col0 = (tid % 16) * 8;
    const int K = D_DIM, N = D_DIM;

    const float* Ag = A + (size_t)bm * 128 * K;
    const float* Bg = B + (size_t)bn * 128;

    float acc[8][8];
    #pragma unroll
    for (int i = 0; i < 8; ++i)
        #pragma unroll
        for (int j = 0; j < 8; ++j) acc[i][j] = 0.0f;

    float a_frag[8], b_frag[8];

    for (int k0 = 0; k0 < K; k0 += 16) {
        #pragma unroll
        for (int ld = 0; ld < 2; ++ld) {
            int idx = tid + ld * 256;
            int r = idx >> 2, c = (idx & 3) * 4;
            float4 v = *reinterpret_cast<const float4*>(Ag + (size_t)r * K + k0 + c);
            As[c + 0][r] = v.x; As[c + 1][r] = v.y; As[c + 2][r] = v.z; As[c + 3][r] = v.w;
        }
        #pragma unroll
        for (int ld = 0; ld < 2; ++ld) {
            int idx = tid + ld * 256;
            int r = idx >> 5, c = (idx & 31) * 4;
            *reinterpret_cast<float4*>(&Bs[r][c]) =
                *reinterpret_cast<const float4*>(Bg + (size_t)(k0 + r) * N + c);
        }
        __syncthreads();
        #pragma unroll
        for (int kk = 0; kk < 16; ++kk) {
            #pragma unroll
            for (int i = 0; i < 8; i += 4)
                *reinterpret_cast<float4*>(&a_frag[i]) = *reinterpret_cast<const float4*>(&As[kk][row0 + i]);
            #pragma unroll
            for (int j = 0; j < 8; j += 4)
                *reinterpret_cast<float4*>(&b_frag[j]) = *reinterpret_cast<const float4*>(&Bs[kk][col0 + j]);
            #pragma unroll
            for (int i = 0; i < 8; ++i)
                #pragma unroll
                for (int j = 0; j < 8; ++j)
                    acc[i][j] = fmaf(a_frag[i], b_frag[j], acc[i][j]);
        }
        __syncthreads();
    }

    float c[16];
    #pragma unroll
    for (int t = 0; t < 16; ++t) c[t] = cb[t];

    const int dbase = bn * 128 + col0;
    float safe[8];
    #pragma unroll
    for (int j = 0; j < 8; ++j) {
        float lv = lx[dbase + j];
        safe[j] = (fabsf(lv) < 1e-8f) ? 1e-8f : lv;
    }

    #pragma unroll
    for (int i = 0; i < 8; ++i) {
        __half hv[8];
        #pragma unroll
        for (int j = 0; j < 8; ++j) {
            float z = acc[i][j] / safe[j];
            float q = c[0];
            #pragma unroll
            for (int t = 0; t < 15; ++t) {
                float mid = 0.5f * (c[t] + c[t + 1]);
                q = (z > mid) ? c[t + 1] : q;
            }
            hv[j] = __float2half(q);
        }
        *reinterpret_cast<uint4*>(&g_Aq[(size_t)(bm * 128 + row0 + i) * D_DIM + dbase]) =
            *reinterpret_cast<uint4*>(hv);
    }
}

// ---------------------------------------------------------------------------
// GEMM2 — fp16 mma.sync, 128(M)x256(N) CTA tile, BK=64, 3-stage cp.async.
// 256 threads: 8 warps as 2(m) x 4(n); warp tile 64x64. K = 2048.
// ---------------------------------------------------------------------------
#define BKK 64
#define STAGES 3
#define A_ROW_B 144                     // 64 fp16 + 8 pad
#define B_ROW_B 528                     // 256 fp16 + 8 pad (odd * 16B)
#define A_STG (128 * A_ROW_B)           // 18432
#define B_STG (64 * B_ROW_B)            // 33792
#define STG_B (A_STG + B_STG)           // 52224
#define SMEM2_TOTAL (STAGES * STG_B)    // 156672

__global__ __launch_bounds__(256, 1)
void gemm2_mma_kernel(float* __restrict__ C)
{
    extern __shared__ __align__(128) unsigned char sm2[];
    const uint32_t sb = smem_u32(sm2);
    const int tid  = threadIdx.x;
    const int lane = tid & 31;
    const int wid  = tid >> 5;
    const int wm   = wid >> 2;          // 0..1
    const int wn   = wid & 3;           // 0..3
    const int m0   = blockIdx.x * 128;  // 32 (fast dim: share B slab in L2)
    const int n0   = blockIdx.y * 256;  // 125

    float acc[4][8][4];
    #pragma unroll
    for (int mi = 0; mi < 4; ++mi)
        #pragma unroll
        for (int ni = 0; ni < 8; ++ni)
            #pragma unroll
            for (int r = 0; r < 4; ++r) acc[mi][ni][r] = 0.0f;

    auto load_stage = [&](int kt, int slot) {
        const int kb = kt * BKK;
        const uint32_t sa  = sb + slot * STG_B;
        const uint32_t sbB = sa + A_STG;
        #pragma unroll
        for (int i = 0; i < 4; ++i) {                   // A: 1024 chunks
            int cc = tid + i * 256;
            int row = cc >> 3, col = (cc & 7) * 8;
            cp16(sa + row * A_ROW_B + col * 2,
                 g_Aq + (size_t)(m0 + row) * D_DIM + kb + col);
        }
        #pragma unroll
        for (int i = 0; i < 8; ++i) {                   // B: 2048 chunks
            int cc = tid + i * 256;
            int row = cc >> 5, col = (cc & 31) * 8;
            cp16(sbB + row * B_ROW_B + col * 2,
                 g_Wx + (size_t)(kb + row) * V_DIM + n0 + col);
        }
        CP_COMMIT();
    };

    const int KT = D_DIM / BKK;     // 32
    load_stage(0, 0);
    load_stage(1, 1);

    // per-lane ldmatrix address pieces (mapping proven in R4)
    const int a_row_l = wm * 64 + (lane & 15);                 // + mi*16
    const int a_k_l   = (lane >> 4) * 8;                       // + ks*16
    const int b_row_l = (lane & 7) + ((lane >> 3) & 1) * 8;    // + ks*16
    const int b_col_l = wn * 64 + ((lane >> 4) & 1) * 8;       // + ni2*16

    int slot = 0;
    for (int kt = 0; kt < KT; ++kt) {
        CP_WAIT1();
        __syncthreads();
        const uint32_t sa  = sb + slot * STG_B;
        const uint32_t sbb = sa + A_STG;

        #pragma unroll
        for (int ks = 0; ks < 4; ++ks) {
            uint32_t a[4][4], b[4][4];
            #pragma unroll
            for (int mi = 0; mi < 4; ++mi)
                ldsm4(a[mi], sa + (a_row_l + mi * 16) * A_ROW_B + (a_k_l + ks * 16) * 2);
            #pragma unroll
            for (int ni2 = 0; ni2 < 4; ++ni2)
                ldsm4t(b[ni2], sbb + (b_row_l + ks * 16) * B_ROW_B + (b_col_l + ni2 * 16) * 2);
            #pragma unroll
            for (int mi = 0; mi < 4; ++mi)
                #pragma unroll
                for (int ni = 0; ni < 8; ++ni)
                    mma16816(acc[mi][ni], a[mi], b[ni >> 1][2 * (ni & 1)],
                             b[ni >> 1][2 * (ni & 1) + 1]);
        }

        if (kt + 2 < KT) load_stage(kt + 2, (slot + 2) % STAGES);
        else CP_COMMIT();           // keep group counting uniform
        slot = (slot + 1) % STAGES;
    }

    // epilogue: fp32 accumulators -> C
    #pragma unroll
    for (int mi = 0; mi < 4; ++mi) {
        const int row = m0 + wm * 64 + mi * 16 + (lane >> 2);
        #pragma unroll
        for (int ni = 0; ni < 8; ++ni) {
            const int col = n0 + wn * 64 + ni * 8 + (lane & 3) * 2;
            float2 v0 = make_float2(acc[mi][ni][0], acc[mi][ni][1]);
            float2 v1 = make_float2(acc[mi][ni][2], acc[mi][ni][3]);
            *reinterpret_cast<float2*>(C + (size_t)row * V_DIM + col) = v0;
            *reinterpret_cast<float2*>(C + (size_t)(row + 8) * V_DIM + col) = v1;
        }
    }
}

// ---------------------------------------------------------------------------
extern "C" void kernel_launch(void* const* d_in, const int* in_sizes, int n_in,
                              void* d_out, int out_size)
{
    const float* x  = (const float*)d_in[0];
    const float* U  = (const float*)d_in[1];
    const float* lx = (const float*)d_in[2];
    const float* lw = (const float*)d_in[3];
    const float* Zw = (const float*)d_in[4];
    const float* cb = (const float*)d_in[5];
    float* out = (float*)d_out;

    cudaFuncSetAttribute(gemm2_mma_kernel,
                         cudaFuncAttributeMaxDynamicSharedMemorySize, SMEM2_TOTAL);

    // 1) Wh = fp16(coeff * Z_w)    (65.536M elems, 4 per thread)
    wprep_kernel<<<(D_DIM * V_DIM / 4) / 256, 256>>>(Zw, lx, lw);

    // 2) x@U + quantize -> fp16 A
    gemm1_quant_kernel<<<dim3(D_DIM / 128, N_TOK / 128), 256>>>(x, U, lx, cb);

    // 3) big GEMM on tensor cores, K=2048
    gemm2_mma_kernel<<<dim3(N_TOK / 128, V_DIM / 256), 256, SMEM2_TOTAL>>>(out);
}

// round 9
// speedup vs baseline: 6.8770x; 1.2743x over previous
#include <cuda_runtime.h>
#include <cuda_fp16.h>
#include <cstdint>

// ---------------------------------------------------------------------------
// QuantizedLMHead (sm_103 baseline ISA):
//   prep:  Wh = fp16((lx*lw)*Z_w)              -> g_Wx  [2048, 32000]
//          x -> xh + 2^-11*xl'  (xl' fp16, SCALED residual, normal range)
//          U -> Uh + 2^-11*Ul'  (Ul' fp16, SCALED residual, normal range)
//   GEMM1: acc  = xl'@Uh + xh@Ul'   (passes 0,1: scaled corrections)
//          acc *= 2^-11; acc += xh@Uh (pass 2)   => s to ~1e-7 rel
//          + nearest-codebook quantize epilogue -> fp16 g_Aq
//   GEMM2: logits = A @ Wh (mma.sync m16n8k16, fp32 acc, K=2048)
//
// R8 fix: UNSCALED residuals fell into fp16 subnormal range (spacing 6e-8),
// losing their mantissa -> z-error ~1e-5 -> 5x extra quantization flips
// (rel_err 2.56e-3). Scaling residuals by 2^11 keeps them normal-fp16.
// ---------------------------------------------------------------------------

#define D_DIM 2048
#define V_DIM 32000
#define N_TOK 4096
#define RES_SCALE 2048.0f
#define RES_INV   (1.0f / 2048.0f)

__device__ __align__(256) __half g_Aq[(size_t)N_TOK * D_DIM];   // 16.8 MB
__device__ __align__(256) __half g_Wx[(size_t)D_DIM * V_DIM];   // 131 MB
__device__ __align__(256) __half g_xh[(size_t)N_TOK * D_DIM];
__device__ __align__(256) __half g_xl[(size_t)N_TOK * D_DIM];   // scaled by 2^11
__device__ __align__(256) __half g_Uh[(size_t)D_DIM * D_DIM];
__device__ __align__(256) __half g_Ul[(size_t)D_DIM * D_DIM];   // scaled by 2^11

// ---------------- PTX helpers ----------------------------------------------
__device__ __forceinline__ uint32_t smem_u32(const void* p) {
    uint32_t a;
    asm("{ .reg .u64 t; cvta.to.shared.u64 t, %1; cvt.u32.u64 %0, t; }" : "=r"(a) : "l"(p));
    return a;
}
__device__ __forceinline__ void cp16(uint32_t dst, const void* src) {
    asm volatile("cp.async.cg.shared.global [%0], [%1], 16;" :: "r"(dst), "l"(src));
}
#define CP_COMMIT() asm volatile("cp.async.commit_group;" ::: "memory")
#define CP_WAIT2()  asm volatile("cp.async.wait_group 2;" ::: "memory")

__device__ __forceinline__ void ldsm4(uint32_t* r, uint32_t addr) {
    asm volatile("ldmatrix.sync.aligned.m8n8.x4.shared.b16 {%0,%1,%2,%3}, [%4];"
                 : "=r"(r[0]), "=r"(r[1]), "=r"(r[2]), "=r"(r[3]) : "r"(addr));
}
__device__ __forceinline__ void ldsm4t(uint32_t* r, uint32_t addr) {
    asm volatile("ldmatrix.sync.aligned.m8n8.x4.trans.shared.b16 {%0,%1,%2,%3}, [%4];"
                 : "=r"(r[0]), "=r"(r[1]), "=r"(r[2]), "=r"(r[3]) : "r"(addr));
}
__device__ __forceinline__ void mma16816(float* c, const uint32_t* a, uint32_t b0, uint32_t b1) {
    asm volatile("mma.sync.aligned.m16n8k16.row.col.f32.f16.f16.f32 "
                 "{%0,%1,%2,%3}, {%4,%5,%6,%7}, {%8,%9}, {%0,%1,%2,%3};"
                 : "+f"(c[0]), "+f"(c[1]), "+f"(c[2]), "+f"(c[3])
                 : "r"(a[0]), "r"(a[1]), "r"(a[2]), "r"(a[3]), "r"(b0), "r"(b1));
}

// ---------------------------------------------------------------------------
// Prep kernels
// ---------------------------------------------------------------------------
__global__ __launch_bounds__(256)
void wprep_kernel(const float* __restrict__ Zw, const float* __restrict__ lx,
                  const float* __restrict__ lw)
{
    const int idx = blockIdx.x * 256 + threadIdx.x;
    const int k   = idx / (V_DIM / 4);
    const int v4  = idx % (V_DIM / 4);
    const float coeff = __ldg(lx + k) * __ldg(lw + k);
    float4 w = *reinterpret_cast<const float4*>(Zw + (size_t)k * V_DIM + v4 * 4);
    __half h[4];
    h[0] = __float2half(coeff * w.x);
    h[1] = __float2half(coeff * w.y);
    h[2] = __float2half(coeff * w.z);
    h[3] = __float2half(coeff * w.w);
    *reinterpret_cast<uint2*>(g_Wx + (size_t)k * V_DIM + v4 * 4) =
        *reinterpret_cast<uint2*>(h);
}

// split fp32 -> fp16 hi + SCALED fp16 residual (x2048, stays in normal range)
template <int WHICH>   // 0: x -> g_xh/g_xl, 1: U -> g_Uh/g_Ul
__global__ __launch_bounds__(256)
void split_kernel(const float* __restrict__ src)
{
    __half* hi = (WHICH == 0) ? g_xh : g_Uh;
    __half* lo = (WHICH == 0) ? g_xl : g_Ul;
    const size_t i4 = ((size_t)blockIdx.x * 256 + threadIdx.x) * 4;
    float4 v = *reinterpret_cast<const float4*>(src + i4);
    __half h[4], l[4];
    h[0] = __float2half(v.x); l[0] = __float2half((v.x - __half2float(h[0])) * RES_SCALE);
    h[1] = __float2half(v.y); l[1] = __float2half((v.y - __half2float(h[1])) * RES_SCALE);
    h[2] = __float2half(v.z); l[2] = __float2half((v.z - __half2float(h[2])) * RES_SCALE);
    h[3] = __float2half(v.w); l[3] = __float2half((v.w - __half2float(h[3])) * RES_SCALE);
    *reinterpret_cast<uint2*>(hi + i4) = *reinterpret_cast<uint2*>(h);
    *reinterpret_cast<uint2*>(lo + i4) = *reinterpret_cast<uint2*>(l);
}

// ---------------------------------------------------------------------------
// Shared GEMM tiling constants: 128(M)x256(N), BK=64, 4-stage cp.async,
// 8 warps 2(m)x4(n), warp tile 64x64.
// ---------------------------------------------------------------------------
#define BKK 64
#define STAGES 4
#define A_ROW_B 144                     // 64 fp16 + 8 pad
#define B_ROW_B 528                     // 256 fp16 + 8 pad (odd * 16B)
#define A_STG (128 * A_ROW_B)           // 18432
#define B_STG (64 * B_ROW_B)            // 33792
#define STG_B (A_STG + B_STG)           // 52224
#define SMEM_MMA (STAGES * STG_B)       // 208896

// ---------------------------------------------------------------------------
// GEMM1 — acc = xl'@Uh + xh@Ul'; acc *= 2^-11; acc += xh@Uh; quantize -> g_Aq.
// grid (N_TOK/128, D_DIM/256) = (32, 8). K_ext = 3*2048.
// Pass order: 0 = lh (xl'@Uh), 1 = hl (xh@Ul'), 2 = hh (xh@Uh).
// ---------------------------------------------------------------------------
__global__ __launch_bounds__(256, 1)
void gemm1_mma_kernel(const float* __restrict__ lx, const float* __restrict__ cb)
{
    extern __shared__ __align__(128) unsigned char sm1[];
    const uint32_t sb = smem_u32(sm1);
    const int tid  = threadIdx.x;
    const int lane = tid & 31;
    const int wid  = tid >> 5;
    const int wm   = wid >> 2;
    const int wn   = wid & 3;
    const int m0   = blockIdx.x * 128;
    const int n0   = blockIdx.y * 256;

    float acc[4][8][4];
    #pragma unroll
    for (int mi = 0; mi < 4; ++mi)
        #pragma unroll
        for (int ni = 0; ni < 8; ++ni)
            #pragma unroll
            for (int r = 0; r < 4; ++r) acc[mi][ni][r] = 0.0f;

    auto load_stage = [&](int kt, int slot) {
        const int p  = kt >> 5;            // pass: 0=lh, 1=hl, 2=hh
        const int kb = (kt & 31) * BKK;
        const __half* Ab = (p == 0) ? g_xl : g_xh;
        const __half* Bb = (p == 1) ? g_Ul : g_Uh;
        const uint32_t sa  = sb + slot * STG_B;
        const uint32_t sbB = sa + A_STG;
        #pragma unroll
        for (int i = 0; i < 4; ++i) {
            int cc = tid + i * 256;
            int row = cc >> 3, col = (cc & 7) * 8;
            cp16(sa + row * A_ROW_B + col * 2,
                 Ab + (size_t)(m0 + row) * D_DIM + kb + col);
        }
        #pragma unroll
        for (int i = 0; i < 8; ++i) {
            int cc = tid + i * 256;
            int row = cc >> 5, col = (cc & 31) * 8;
            cp16(sbB + row * B_ROW_B + col * 2,
                 Bb + (size_t)(kb + row) * D_DIM + n0 + col);
        }
        CP_COMMIT();
    };

    const int KT = 3 * (D_DIM / BKK);    // 96
    load_stage(0, 0);
    load_stage(1, 1);
    load_stage(2, 2);

    const int a_row_l = wm * 64 + (lane & 15);
    const int a_k_l   = (lane >> 4) * 8;
    const int b_row_l = (lane & 7) + ((lane >> 3) & 1) * 8;
    const int b_col_l = wn * 64 + ((lane >> 4) & 1) * 8;

    for (int kt = 0; kt < KT; ++kt) {
        // boundary between correction passes and the hh pass:
        // acc currently holds 2^11*(xl@Uh + xh@Ul) -> scale down once.
        if (kt == 64) {
            #pragma unroll
            for (int mi = 0; mi < 4; ++mi)
                #pragma unroll
                for (int ni = 0; ni < 8; ++ni)
                    #pragma unroll
                    for (int r = 0; r < 4; ++r)
                        acc[mi][ni][r] *= RES_INV;
        }

        CP_WAIT2();
        __syncthreads();
        const int slot = kt & (STAGES - 1);
        const uint32_t sa  = sb + slot * STG_B;
        const uint32_t sbb = sa + A_STG;

        #pragma unroll
        for (int ks = 0; ks < 4; ++ks) {
            uint32_t a[4][4], b[4][4];
            #pragma unroll
            for (int mi = 0; mi < 4; ++mi)
                ldsm4(a[mi], sa + (a_row_l + mi * 16) * A_ROW_B + (a_k_l + ks * 16) * 2);
            #pragma unroll
            for (int ni2 = 0; ni2 < 4; ++ni2)
                ldsm4t(b[ni2], sbb + (b_row_l + ks * 16) * B_ROW_B + (b_col_l + ni2 * 16) * 2);
            #pragma unroll
            for (int mi = 0; mi < 4; ++mi)
                #pragma unroll
                for (int ni = 0; ni < 8; ++ni)
                    mma16816(acc[mi][ni], a[mi], b[ni >> 1][2 * (ni & 1)],
                             b[ni >> 1][2 * (ni & 1) + 1]);
        }

        if (kt + STAGES - 1 < KT) load_stage(kt + STAGES - 1, (kt + STAGES - 1) & (STAGES - 1));
        else CP_COMMIT();
        __syncthreads();
    }

    // epilogue: quantize s -> codebook value (tie -> lower index), store fp16
    float c[16];
    #pragma unroll
    for (int t = 0; t < 16; ++t) c[t] = cb[t];

    #pragma unroll
    for (int ni = 0; ni < 8; ++ni) {
        const int c0 = n0 + wn * 64 + ni * 8 + (lane & 3) * 2;
        float l0 = lx[c0], l1 = lx[c0 + 1];
        float s0 = (fabsf(l0) < 1e-8f) ? 1e-8f : l0;
        float s1 = (fabsf(l1) < 1e-8f) ? 1e-8f : l1;
        #pragma unroll
        for (int mi = 0; mi < 4; ++mi) {
            const int r0 = m0 + wm * 64 + mi * 16 + (lane >> 2);
            #pragma unroll
            for (int half_i = 0; half_i < 2; ++half_i) {
                float z0 = acc[mi][ni][2 * half_i]     / s0;
                float z1 = acc[mi][ni][2 * half_i + 1] / s1;
                float q0 = c[0], q1 = c[0];
                #pragma unroll
                for (int t = 0; t < 15; ++t) {
                    float mid = 0.5f * (c[t] + c[t + 1]);
                    q0 = (z0 > mid) ? c[t + 1] : q0;
                    q1 = (z1 > mid) ? c[t + 1] : q1;
                }
                __half2 hv = __halves2half2(__float2half(q0), __float2half(q1));
                *reinterpret_cast<uint32_t*>(
                    &g_Aq[(size_t)(r0 + 8 * half_i) * D_DIM + c0]) =
                    *reinterpret_cast<uint32_t*>(&hv);
            }
        }
    }
}

// ---------------------------------------------------------------------------
// GEMM2 — logits = A @ Wh. grid (N_TOK/128, V_DIM/256). K = 2048.
// ---------------------------------------------------------------------------
__global__ __launch_bounds__(256, 1)
void gemm2_mma_kernel(float* __restrict__ C)
{
    extern __shared__ __align__(128) unsigned char sm2[];
    const uint32_t sb = smem_u32(sm2);
    const int tid  = threadIdx.x;
    const int lane = tid & 31;
    const int wid  = tid >> 5;
    const int wm   = wid >> 2;
    const int wn   = wid & 3;
    const int m0   = blockIdx.x * 128;
    const int n0   = blockIdx.y * 256;

    float acc[4][8][4];
    #pragma unroll
    for (int mi = 0; mi < 4; ++mi)
        #pragma unroll
        for (int ni = 0; ni < 8; ++ni)
            #pragma unroll
            for (int r = 0; r < 4; ++r) acc[mi][ni][r] = 0.0f;

    auto load_stage = [&](int kt, int slot) {
        const int kb = kt * BKK;
        const uint32_t sa  = sb + slot * STG_B;
        const uint32_t sbB = sa + A_STG;
        #pragma unroll
        for (int i = 0; i < 4; ++i) {
            int cc = tid + i * 256;
            int row = cc >> 3, col = (cc & 7) * 8;
            cp16(sa + row * A_ROW_B + col * 2,
                 g_Aq + (size_t)(m0 + row) * D_DIM + kb + col);
        }
        #pragma unroll
        for (int i = 0; i < 8; ++i) {
            int cc = tid + i * 256;
            int row = cc >> 5, col = (cc & 31) * 8;
            cp16(sbB + row * B_ROW_B + col * 2,
                 g_Wx + (size_t)(kb + row) * V_DIM + n0 + col);
        }
        CP_COMMIT();
    };

    const int KT = D_DIM / BKK;     // 32
    load_stage(0, 0);
    load_stage(1, 1);
    load_stage(2, 2);

    const int a_row_l = wm * 64 + (lane & 15);
    const int a_k_l   = (lane >> 4) * 8;
    const int b_row_l = (lane & 7) + ((lane >> 3) & 1) * 8;
    const int b_col_l = wn * 64 + ((lane >> 4) & 1) * 8;

    for (int kt = 0; kt < KT; ++kt) {
        CP_WAIT2();
        __syncthreads();
        const int slot = kt & (STAGES - 1);
        const uint32_t sa  = sb + slot * STG_B;
        const uint32_t sbb = sa + A_STG;

        #pragma unroll
        for (int ks = 0; ks < 4; ++ks) {
            uint32_t a[4][4], b[4][4];
            #pragma unroll
            for (int mi = 0; mi < 4; ++mi)
                ldsm4(a[mi], sa + (a_row_l + mi * 16) * A_ROW_B + (a_k_l + ks * 16) * 2);
            #pragma unroll
            for (int ni2 = 0; ni2 < 4; ++ni2)
                ldsm4t(b[ni2], sbb + (b_row_l + ks * 16) * B_ROW_B + (b_col_l + ni2 * 16) * 2);
            #pragma unroll
            for (int mi = 0; mi < 4; ++mi)
                #pragma unroll
                for (int ni = 0; ni < 8; ++ni)
                    mma16816(acc[mi][ni], a[mi], b[ni >> 1][2 * (ni & 1)],
                             b[ni >> 1][2 * (ni & 1) + 1]);
        }

        if (kt + STAGES - 1 < KT) load_stage(kt + STAGES - 1, (kt + STAGES - 1) & (STAGES - 1));
        else CP_COMMIT();
        __syncthreads();
    }

    #pragma unroll
    for (int mi = 0; mi < 4; ++mi) {
        const int row = m0 + wm * 64 + mi * 16 + (lane >> 2);
        #pragma unroll
        for (int ni = 0; ni < 8; ++ni) {
            const int col = n0 + wn * 64 + ni * 8 + (lane & 3) * 2;
            float2 v0 = make_float2(acc[mi][ni][0], acc[mi][ni][1]);
            float2 v1 = make_float2(acc[mi][ni][2], acc[mi][ni][3]);
            *reinterpret_cast<float2*>(C + (size_t)row * V_DIM + col) = v0;
            *reinterpret_cast<float2*>(C + (size_t)(row + 8) * V_DIM + col) = v1;
        }
    }
}

// ---------------------------------------------------------------------------
extern "C" void kernel_launch(void* const* d_in, const int* in_sizes, int n_in,
                              void* d_out, int out_size)
{
    const float* x  = (const float*)d_in[0];
    const float* U  = (const float*)d_in[1];
    const float* lx = (const float*)d_in[2];
    const float* lw = (const float*)d_in[3];
    const float* Zw = (const float*)d_in[4];
    const float* cb = (const float*)d_in[5];
    float* out = (float*)d_out;

    cudaFuncSetAttribute(gemm1_mma_kernel,
                         cudaFuncAttributeMaxDynamicSharedMemorySize, SMEM_MMA);
    cudaFuncSetAttribute(gemm2_mma_kernel,
                         cudaFuncAttributeMaxDynamicSharedMemorySize, SMEM_MMA);

    // prep
    wprep_kernel<<<(D_DIM * V_DIM / 4) / 256, 256>>>(Zw, lx, lw);
    split_kernel<0><<<((size_t)N_TOK * D_DIM / 4) / 256, 256>>>(x);
    split_kernel<1><<<((size_t)D_DIM * D_DIM / 4) / 256, 256>>>(U);

    // GEMM1 (tensor cores, scaled-residual 3-pass) + quantize -> g_Aq
    gemm1_mma_kernel<<<dim3(N_TOK / 128, D_DIM / 256), 256, SMEM_MMA>>>(lx, cb);

    // GEMM2 (tensor cores) -> logits
    gemm2_mma_kernel<<<dim3(N_TOK / 128, V_DIM / 256), 256, SMEM_MMA>>>(out);
}

// round 10
// speedup vs baseline: 7.2973x; 1.0611x over previous
#include <cuda_runtime.h>
#include <cuda_fp16.h>
#include <cstdint>

// ---------------------------------------------------------------------------
// QuantizedLMHead (sm_103 baseline ISA):
//   prep:  Wh = fp16((lx*lw)*Z_w)              -> g_Wx  [2048, 32000]
//          x -> xh + 2^-11*xl'  (scaled fp16 residual)
//          U -> Uh + 2^-11*Ul'  (scaled fp16 residual)
//   GEMM1: acc = xl'@Uh + xh@Ul'; acc *= 2^-11; acc += xh@Uh
//          + nearest-codebook quantize epilogue -> fp16 g_Aq
//   GEMM2: logits = A @ Wh (mma.sync m16n8k16, fp32 acc, K=2048)
//
// R9: 512-thread CTAs (16 warps, 2x8, warp tile 64x32, ~120 regs) to double
// warps/SMSP (2->4) and lift tensor-pipe utilization. Numerics unchanged.
// ---------------------------------------------------------------------------

#define D_DIM 2048
#define V_DIM 32000
#define N_TOK 4096
#define RES_SCALE 2048.0f
#define RES_INV   (1.0f / 2048.0f)

__device__ __align__(256) __half g_Aq[(size_t)N_TOK * D_DIM];   // 16.8 MB
__device__ __align__(256) __half g_Wx[(size_t)D_DIM * V_DIM];   // 131 MB
__device__ __align__(256) __half g_xh[(size_t)N_TOK * D_DIM];
__device__ __align__(256) __half g_xl[(size_t)N_TOK * D_DIM];   // scaled 2^11
__device__ __align__(256) __half g_Uh[(size_t)D_DIM * D_DIM];
__device__ __align__(256) __half g_Ul[(size_t)D_DIM * D_DIM];   // scaled 2^11

// ---------------- PTX helpers ----------------------------------------------
__device__ __forceinline__ uint32_t smem_u32(const void* p) {
    uint32_t a;
    asm("{ .reg .u64 t; cvta.to.shared.u64 t, %1; cvt.u32.u64 %0, t; }" : "=r"(a) : "l"(p));
    return a;
}
__device__ __forceinline__ void cp16(uint32_t dst, const void* src) {
    asm volatile("cp.async.cg.shared.global [%0], [%1], 16;" :: "r"(dst), "l"(src));
}
#define CP_COMMIT() asm volatile("cp.async.commit_group;" ::: "memory")
#define CP_WAIT2()  asm volatile("cp.async.wait_group 2;" ::: "memory")

__device__ __forceinline__ void ldsm4(uint32_t* r, uint32_t addr) {
    asm volatile("ldmatrix.sync.aligned.m8n8.x4.shared.b16 {%0,%1,%2,%3}, [%4];"
                 : "=r"(r[0]), "=r"(r[1]), "=r"(r[2]), "=r"(r[3]) : "r"(addr));
}
__device__ __forceinline__ void ldsm4t(uint32_t* r, uint32_t addr) {
    asm volatile("ldmatrix.sync.aligned.m8n8.x4.trans.shared.b16 {%0,%1,%2,%3}, [%4];"
                 : "=r"(r[0]), "=r"(r[1]), "=r"(r[2]), "=r"(r[3]) : "r"(addr));
}
__device__ __forceinline__ void mma16816(float* c, const uint32_t* a, uint32_t b0, uint32_t b1) {
    asm volatile("mma.sync.aligned.m16n8k16.row.col.f32.f16.f16.f32 "
                 "{%0,%1,%2,%3}, {%4,%5,%6,%7}, {%8,%9}, {%0,%1,%2,%3};"
                 : "+f"(c[0]), "+f"(c[1]), "+f"(c[2]), "+f"(c[3])
                 : "r"(a[0]), "r"(a[1]), "r"(a[2]), "r"(a[3]), "r"(b0), "r"(b1));
}

// ---------------------------------------------------------------------------
// Prep kernels (unchanged from R8)
// ---------------------------------------------------------------------------
__global__ __launch_bounds__(256)
void wprep_kernel(const float* __restrict__ Zw, const float* __restrict__ lx,
                  const float* __restrict__ lw)
{
    const int idx = blockIdx.x * 256 + threadIdx.x;
    const int k   = idx / (V_DIM / 4);
    const int v4  = idx % (V_DIM / 4);
    const float coeff = __ldg(lx + k) * __ldg(lw + k);
    float4 w = *reinterpret_cast<const float4*>(Zw + (size_t)k * V_DIM + v4 * 4);
    __half h[4];
    h[0] = __float2half(coeff * w.x);
    h[1] = __float2half(coeff * w.y);
    h[2] = __float2half(coeff * w.z);
    h[3] = __float2half(coeff * w.w);
    *reinterpret_cast<uint2*>(g_Wx + (size_t)k * V_DIM + v4 * 4) =
        *reinterpret_cast<uint2*>(h);
}

template <int WHICH>   // 0: x -> g_xh/g_xl, 1: U -> g_Uh/g_Ul
__global__ __launch_bounds__(256)
void split_kernel(const float* __restrict__ src)
{
    __half* hi = (WHICH == 0) ? g_xh : g_Uh;
    __half* lo = (WHICH == 0) ? g_xl : g_Ul;
    const size_t i4 = ((size_t)blockIdx.x * 256 + threadIdx.x) * 4;
    float4 v = *reinterpret_cast<const float4*>(src + i4);
    __half h[4], l[4];
    h[0] = __float2half(v.x); l[0] = __float2half((v.x - __half2float(h[0])) * RES_SCALE);
    h[1] = __float2half(v.y); l[1] = __float2half((v.y - __half2float(h[1])) * RES_SCALE);
    h[2] = __float2half(v.z); l[2] = __float2half((v.z - __half2float(h[2])) * RES_SCALE);
    h[3] = __float2half(v.w); l[3] = __float2half((v.w - __half2float(h[3])) * RES_SCALE);
    *reinterpret_cast<uint2*>(hi + i4) = *reinterpret_cast<uint2*>(h);
    *reinterpret_cast<uint2*>(lo + i4) = *reinterpret_cast<uint2*>(l);
}

// ---------------------------------------------------------------------------
// GEMM tiling: 128(M)x256(N) CTA tile, BK=64, 4-stage cp.async,
// 512 threads = 16 warps as 2(m)x8(n), warp tile 64x32.
// ---------------------------------------------------------------------------
#define BKK 64
#define STAGES 4
#define A_ROW_B 144                     // 64 fp16 + 8 pad
#define B_ROW_B 528                     // 256 fp16 + 8 pad (odd * 16B)
#define A_STG (128 * A_ROW_B)           // 18432
#define B_STG (64 * B_ROW_B)            // 33792
#define STG_B (A_STG + B_STG)           // 52224
#define SMEM_MMA (STAGES * STG_B)       // 208896
#define NTHREADS 512

// ---------------------------------------------------------------------------
// GEMM1 — scaled-residual 3-pass + quantize -> g_Aq.
// grid (N_TOK/128, D_DIM/256) = (32, 8). K_ext = 3*2048.
// ---------------------------------------------------------------------------
__global__ __launch_bounds__(NTHREADS, 1)
void gemm1_mma_kernel(const float* __restrict__ lx, const float* __restrict__ cb)
{
    extern __shared__ __align__(128) unsigned char sm1[];
    const uint32_t sb = smem_u32(sm1);
    const int tid  = threadIdx.x;
    const int lane = tid & 31;
    const int wid  = tid >> 5;
    const int wm   = wid >> 3;          // 0..1
    const int wn   = wid & 7;           // 0..7
    const int m0   = blockIdx.x * 128;
    const int n0   = blockIdx.y * 256;

    float acc[4][4][4];
    #pragma unroll
    for (int mi = 0; mi < 4; ++mi)
        #pragma unroll
        for (int ni = 0; ni < 4; ++ni)
            #pragma unroll
            for (int r = 0; r < 4; ++r) acc[mi][ni][r] = 0.0f;

    auto load_stage = [&](int kt, int slot) {
        const int p  = kt >> 5;            // pass: 0=lh, 1=hl, 2=hh
        const int kb = (kt & 31) * BKK;
        const __half* Ab = (p == 0) ? g_xl : g_xh;
        const __half* Bb = (p == 1) ? g_Ul : g_Uh;
        const uint32_t sa  = sb + slot * STG_B;
        const uint32_t sbB = sa + A_STG;
        #pragma unroll
        for (int i = 0; i < 2; ++i) {                   // A: 1024 chunks
            int cc = tid + i * NTHREADS;
            int row = cc >> 3, col = (cc & 7) * 8;
            cp16(sa + row * A_ROW_B + col * 2,
                 Ab + (size_t)(m0 + row) * D_DIM + kb + col);
        }
        #pragma unroll
        for (int i = 0; i < 4; ++i) {                   // B: 2048 chunks
            int cc = tid + i * NTHREADS;
            int row = cc >> 5, col = (cc & 31) * 8;
            cp16(sbB + row * B_ROW_B + col * 2,
                 Bb + (size_t)(kb + row) * D_DIM + n0 + col);
        }
        CP_COMMIT();
    };

    const int KT = 3 * (D_DIM / BKK);    // 96
    load_stage(0, 0);
    load_stage(1, 1);
    load_stage(2, 2);

    const int a_row_l = wm * 64 + (lane & 15);
    const int a_k_l   = (lane >> 4) * 8;
    const int b_row_l = (lane & 7) + ((lane >> 3) & 1) * 8;
    const int b_col_l = wn * 32 + ((lane >> 4) & 1) * 8;

    for (int kt = 0; kt < KT; ++kt) {
        if (kt == 64) {   // acc holds 2^11*(lh+hl): rescale once before hh pass
            #pragma unroll
            for (int mi = 0; mi < 4; ++mi)
                #pragma unroll
                for (int ni = 0; ni < 4; ++ni)
                    #pragma unroll
                    for (int r = 0; r < 4; ++r)
                        acc[mi][ni][r] *= RES_INV;
        }

        CP_WAIT2();
        __syncthreads();
        const int slot = kt & (STAGES - 1);
        const uint32_t sa  = sb + slot * STG_B;
        const uint32_t sbb = sa + A_STG;

        #pragma unroll
        for (int ks = 0; ks < 4; ++ks) {
            uint32_t a[4][4], b[2][4];
            #pragma unroll
            for (int mi = 0; mi < 4; ++mi)
                ldsm4(a[mi], sa + (a_row_l + mi * 16) * A_ROW_B + (a_k_l + ks * 16) * 2);
            #pragma unroll
            for (int ni2 = 0; ni2 < 2; ++ni2)
                ldsm4t(b[ni2], sbb + (b_row_l + ks * 16) * B_ROW_B + (b_col_l + ni2 * 16) * 2);
            #pragma unroll
            for (int mi = 0; mi < 4; ++mi)
                #pragma unroll
                for (int ni = 0; ni < 4; ++ni)
                    mma16816(acc[mi][ni], a[mi], b[ni >> 1][2 * (ni & 1)],
                             b[ni >> 1][2 * (ni & 1) + 1]);
        }

        if (kt + STAGES - 1 < KT) load_stage(kt + STAGES - 1, (kt + STAGES - 1) & (STAGES - 1));
        else CP_COMMIT();
    }

    // epilogue: quantize s -> codebook value (tie -> lower index), store fp16
    float c[16];
    #pragma unroll
    for (int t = 0; t < 16; ++t) c[t] = cb[t];

    #pragma unroll
    for (int ni = 0; ni < 4; ++ni) {
        const int c0 = n0 + wn * 32 + ni * 8 + (lane & 3) * 2;
        float l0 = lx[c0], l1 = lx[c0 + 1];
        float s0 = (fabsf(l0) < 1e-8f) ? 1e-8f : l0;
        float s1 = (fabsf(l1) < 1e-8f) ? 1e-8f : l1;
        #pragma unroll
        for (int mi = 0; mi < 4; ++mi) {
            const int r0 = m0 + wm * 64 + mi * 16 + (lane >> 2);
            #pragma unroll
            for (int half_i = 0; half_i < 2; ++half_i) {
                float z0 = acc[mi][ni][2 * half_i]     / s0;
                float z1 = acc[mi][ni][2 * half_i + 1] / s1;
                float q0 = c[0], q1 = c[0];
                #pragma unroll
                for (int t = 0; t < 15; ++t) {
                    float mid = 0.5f * (c[t] + c[t + 1]);
                    q0 = (z0 > mid) ? c[t + 1] : q0;
                    q1 = (z1 > mid) ? c[t + 1] : q1;
                }
                __half2 hv = __halves2half2(__float2half(q0), __float2half(q1));
                *reinterpret_cast<uint32_t*>(
                    &g_Aq[(size_t)(r0 + 8 * half_i) * D_DIM + c0]) =
                    *reinterpret_cast<uint32_t*>(&hv);
            }
        }
    }
}

// ---------------------------------------------------------------------------
// GEMM2 — logits = A @ Wh. grid (N_TOK/128, V_DIM/256). K = 2048.
// ---------------------------------------------------------------------------
__global__ __launch_bounds__(NTHREADS, 1)
void gemm2_mma_kernel(float* __restrict__ C)
{
    extern __shared__ __align__(128) unsigned char sm2[];
    const uint32_t sb = smem_u32(sm2);
    const int tid  = threadIdx.x;
    const int lane = tid & 31;
    const int wid  = tid >> 5;
    const int wm   = wid >> 3;
    const int wn   = wid & 7;
    const int m0   = blockIdx.x * 128;
    const int n0   = blockIdx.y * 256;

    float acc[4][4][4];
    #pragma unroll
    for (int mi = 0; mi < 4; ++mi)
        #pragma unroll
        for (int ni = 0; ni < 4; ++ni)
            #pragma unroll
            for (int r = 0; r < 4; ++r) acc[mi][ni][r] = 0.0f;

    auto load_stage = [&](int kt, int slot) {
        const int kb = kt * BKK;
        const uint32_t sa  = sb + slot * STG_B;
        const uint32_t sbB = sa + A_STG;
        #pragma unroll
        for (int i = 0; i < 2; ++i) {
            int cc = tid + i * NTHREADS;
            int row = cc >> 3, col = (cc & 7) * 8;
            cp16(sa + row * A_ROW_B + col * 2,
                 g_Aq + (size_t)(m0 + row) * D_DIM + kb + col);
        }
        #pragma unroll
        for (int i = 0; i < 4; ++i) {
            int cc = tid + i * NTHREADS;
            int row = cc >> 5, col = (cc & 31) * 8;
            cp16(sbB + row * B_ROW_B + col * 2,
                 g_Wx + (size_t)(kb + row) * V_DIM + n0 + col);
        }
        CP_COMMIT();
    };

    const int KT = D_DIM / BKK;     // 32
    load_stage(0, 0);
    load_stage(1, 1);
    load_stage(2, 2);

    const int a_row_l = wm * 64 + (lane & 15);
    const int a_k_l   = (lane >> 4) * 8;
    const int b_row_l = (lane & 7) + ((lane >> 3) & 1) * 8;
    const int b_col_l = wn * 32 + ((lane >> 4) & 1) * 8;

    for (int kt = 0; kt < KT; ++kt) {
        CP_WAIT2();
        __syncthreads();
        const int slot = kt & (STAGES - 1);
        const uint32_t sa  = sb + slot * STG_B;
        const uint32_t sbb = sa + A_STG;

        #pragma unroll
        for (int ks = 0; ks < 4; ++ks) {
            uint32_t a[4][4], b[2][4];
            #pragma unroll
            for (int mi = 0; mi < 4; ++mi)
                ldsm4(a[mi], sa + (a_row_l + mi * 16) * A_ROW_B + (a_k_l + ks * 16) * 2);
            #pragma unroll
            for (int ni2 = 0; ni2 < 2; ++ni2)
                ldsm4t(b[ni2], sbb + (b_row_l + ks * 16) * B_ROW_B + (b_col_l + ni2 * 16) * 2);
            #pragma unroll
            for (int mi = 0; mi < 4; ++mi)
                #pragma unroll
                for (int ni = 0; ni < 4; ++ni)
                    mma16816(acc[mi][ni], a[mi], b[ni >> 1][2 * (ni & 1)],
                             b[ni >> 1][2 * (ni & 1) + 1]);
        }

        if (kt + STAGES - 1 < KT) load_stage(kt + STAGES - 1, (kt + STAGES - 1) & (STAGES - 1));
        else CP_COMMIT();
    }

    #pragma unroll
    for (int mi = 0; mi < 4; ++mi) {
        const int row = m0 + wm * 64 + mi * 16 + (lane >> 2);
        #pragma unroll
        for (int ni = 0; ni < 4; ++ni) {
            const int col = n0 + wn * 32 + ni * 8 + (lane & 3) * 2;
            float2 v0 = make_float2(acc[mi][ni][0], acc[mi][ni][1]);
            float2 v1 = make_float2(acc[mi][ni][2], acc[mi][ni][3]);
            *reinterpret_cast<float2*>(C + (size_t)row * V_DIM + col) = v0;
            *reinterpret_cast<float2*>(C + (size_t)(row + 8) * V_DIM + col) = v1;
        }
    }
}

// ---------------------------------------------------------------------------
extern "C" void kernel_launch(void* const* d_in, const int* in_sizes, int n_in,
                              void* d_out, int out_size)
{
    const float* x  = (const float*)d_in[0];
    const float* U  = (const float*)d_in[1];
    const float* lx = (const float*)d_in[2];
    const float* lw = (const float*)d_in[3];
    const float* Zw = (const float*)d_in[4];
    const float* cb = (const float*)d_in[5];
    float* out = (float*)d_out;

    cudaFuncSetAttribute(gemm1_mma_kernel,
                         cudaFuncAttributeMaxDynamicSharedMemorySize, SMEM_MMA);
    cudaFuncSetAttribute(gemm2_mma_kernel,
                         cudaFuncAttributeMaxDynamicSharedMemorySize, SMEM_MMA);

    // prep
    wprep_kernel<<<(D_DIM * V_DIM / 4) / 256, 256>>>(Zw, lx, lw);
    split_kernel<0><<<((size_t)N_TOK * D_DIM / 4) / 256, 256>>>(x);
    split_kernel<1><<<((size_t)D_DIM * D_DIM / 4) / 256, 256>>>(U);

    // GEMM1 (scaled-residual 3-pass) + quantize -> g_Aq
    gemm1_mma_kernel<<<dim3(N_TOK / 128, D_DIM / 256), NTHREADS, SMEM_MMA>>>(lx, cb);

    // GEMM2 -> logits
    gemm2_mma_kernel<<<dim3(N_TOK / 128, V_DIM / 256), NTHREADS, SMEM_MMA>>>(out);
}